// round 17
// baseline (speedup 1.0000x reference)
#include <cuda_runtime.h>
#include <cuda_fp16.h>
#include <mma.h>

using namespace nvcuda;

#define N_NODES 50000
#define N_EDGES 800000
#define D 128
#define N_PAD 50048              // 782 * 64, padded row count for guard-free GEMM
#define CAP 96                   // bucket capacity per node (deg ~ Poisson(16))

#define N_TILES   782            // N_PAD / 64
#define TILES_PB  4              // tiles per GEMM block
#define GEMM_GRID 196            // ceil(782 / 4)

#define AS_STRIDE 136            // halfs per A-tile row (272 B: 16B-aligned, 32B frag rows)
#define WS_STRIDE 136
#define AS_HALFS  (64 * AS_STRIDE)
#define WS_HALFS  (128 * WS_STRIDE)
#define CS_FLOATS (64 * 132)
#define GEMM_SMEM ((AS_HALFS + WS_HALFS) * 2 + CS_FLOATS * 4)   // 86016 B

// ---- scratch (device globals; no allocation allowed) ----
__device__ __half g_a  [N_PAD * D];     // 12.8 MB: layer-2 GEMM input (pre-scaled by dinv)
__device__ __half g_xsh[N_PAD * D];     // 12.8 MB: GEMM output (messages)
__device__ __half g_w2 [D * D];
__device__ float  g_dinv[N_NODES];
__device__ int    g_cur [N_NODES];      // per-node incoming-edge count (atomic cursor)
__device__ int    g_bkt [N_NODES * CAP]; // 19.2 MB: padded buckets of source nodes

// ---------------------------------------------------------------------------
// Single-pass bucket build: no histogram, no scan.
__global__ void k_bucket(const int4* __restrict__ row4, const int4* __restrict__ col4) {
    int i = blockIdx.x * blockDim.x + threadIdx.x;
    if (i < N_EDGES / 4) {
        int4 r = __ldg(&row4[i]);
        int4 c = __ldg(&col4[i]);
        g_bkt[c.x * CAP + atomicAdd(&g_cur[c.x], 1)] = r.x;
        g_bkt[c.y * CAP + atomicAdd(&g_cur[c.y], 1)] = r.y;
        g_bkt[c.z * CAP + atomicAdd(&g_cur[c.z], 1)] = r.z;
        g_bkt[c.w * CAP + atomicAdd(&g_cur[c.w], 1)] = r.w;
    }
}

__global__ void k_dinv() {
    int i = blockIdx.x * blockDim.x + threadIdx.x;
    if (i < N_NODES)
        g_dinv[i] = rsqrtf((float)(g_cur[i] + 1));   // +1 self loop -> always > 0
}

// W2 -> fp16 (runs on the side stream, hidden behind layer-1 GEMM)
__global__ void k_conv_w2(const float* __restrict__ W2) {
    int i = blockIdx.x * blockDim.x + threadIdx.x;
    if (i < D * D) g_w2[i] = __float2half_rn(W2[i]);
}

// ---------------------------------------------------------------------------
// Multi-tile tensor-core GEMM: out = A @ W. Each block stages W ONCE in smem,
// then loops over TILES_PB row-tiles of 64. All fragment loads from smem.
// 8 warps 2x4, warp tile 32x32.
// F32IN: A is fp32 (harness x, row-guarded, converted while staging) and W is
//        fp32 (converted while staging). Else both fp16 (padded, guard-free).
template <bool F32IN>
__global__ void __launch_bounds__(256)
k_gemm(const void* __restrict__ Ain, const void* __restrict__ Win,
       __half* __restrict__ out) {
    extern __shared__ __half smp[];
    __half* As = smp;                       // 64 x AS_STRIDE
    __half* Ws = smp + AS_HALFS;            // 128 x WS_STRIDE
    float*  Cs = (float*)(smp + AS_HALFS + WS_HALFS);   // 64 x 132

    const int tid = threadIdx.x;
    const int wid = tid >> 5;
    const int wr  = wid >> 2;               // 0..1
    const int wc  = wid & 3;                // 0..3
    const int col0 = wc * 32;

    // ---- stage W once: 128x128 -> fp16 smem, coalesced ----
    if (F32IN) {
        const float* W = (const float*)Win;
        for (int idx = tid; idx < 128 * 16; idx += 256) {
            int r  = idx >> 4;
            int c8 = (idx & 15) * 8;
            float4 v0 = *(const float4*)&W[(size_t)r * D + c8];
            float4 v1 = *(const float4*)&W[(size_t)r * D + c8 + 4];
            union { __half2 h2[4]; uint4 u; } pk;
            pk.h2[0] = __floats2half2_rn(v0.x, v0.y);
            pk.h2[1] = __floats2half2_rn(v0.z, v0.w);
            pk.h2[2] = __floats2half2_rn(v1.x, v1.y);
            pk.h2[3] = __floats2half2_rn(v1.z, v1.w);
            *(uint4*)&Ws[r * WS_STRIDE + c8] = pk.u;
        }
    } else {
        const __half* W = (const __half*)Win;
        for (int idx = tid; idx < 128 * 16; idx += 256) {
            int r  = idx >> 4;
            int c8 = (idx & 15) * 8;
            *(uint4*)&Ws[r * WS_STRIDE + c8] = *(const uint4*)&W[(size_t)r * D + c8];
        }
    }

    const int t0 = blockIdx.x * TILES_PB;
    const int t1 = min(t0 + TILES_PB, N_TILES);
    for (int tile = t0; tile < t1; tile++) {
        const int rowBase = tile * 64;

        // ---- stage A tile: 64x128 ----
        if (F32IN) {
            const float* A = (const float*)Ain;
            int r  = tid >> 2;              // 0..63
            int c0 = (tid & 3) * 32;        // 0,32,64,96
            int grow = rowBase + r;
            if (grow < N_NODES) {
                const float* src = A + (size_t)grow * D + c0;
#pragma unroll
                for (int q = 0; q < 8; q++) {
                    float4 v = *(const float4*)(src + q * 4);
                    union { __half2 h2[2]; uint2 u; } pk;
                    pk.h2[0] = __floats2half2_rn(v.x, v.y);
                    pk.h2[1] = __floats2half2_rn(v.z, v.w);
                    *(uint2*)&As[r * AS_STRIDE + c0 + q * 4] = pk.u;
                }
            } else {
                uint2 z = make_uint2(0, 0);
#pragma unroll
                for (int q = 0; q < 8; q++) *(uint2*)&As[r * AS_STRIDE + c0 + q * 4] = z;
            }
        } else {
            const __half* A = (const __half*)Ain;
            for (int idx = tid; idx < 64 * 16; idx += 256) {
                int r  = idx >> 4;
                int c8 = (idx & 15) * 8;
                *(uint4*)&As[r * AS_STRIDE + c8] =
                    *(const uint4*)&A[(size_t)(rowBase + r) * D + c8];
            }
        }
        __syncthreads();   // staging done (also: prior epilogue reads finished)

        wmma::fragment<wmma::accumulator, 16, 16, 16, float> acc[2][2];
#pragma unroll
        for (int i = 0; i < 2; i++)
#pragma unroll
            for (int j = 0; j < 2; j++) wmma::fill_fragment(acc[i][j], 0.0f);

#pragma unroll
        for (int k = 0; k < D; k += 16) {
            wmma::fragment<wmma::matrix_a, 16, 16, 16, __half, wmma::row_major> a0, a1;
            wmma::fragment<wmma::matrix_b, 16, 16, 16, __half, wmma::row_major> b0, b1;
            wmma::load_matrix_sync(a0, &As[(wr * 32) * AS_STRIDE + k], AS_STRIDE);
            wmma::load_matrix_sync(a1, &As[(wr * 32 + 16) * AS_STRIDE + k], AS_STRIDE);
            wmma::load_matrix_sync(b0, &Ws[k * WS_STRIDE + col0], WS_STRIDE);
            wmma::load_matrix_sync(b1, &Ws[k * WS_STRIDE + col0 + 16], WS_STRIDE);
            wmma::mma_sync(acc[0][0], a0, b0, acc[0][0]);
            wmma::mma_sync(acc[0][1], a0, b1, acc[0][1]);
            wmma::mma_sync(acc[1][0], a1, b0, acc[1][0]);
            wmma::mma_sync(acc[1][1], a1, b1, acc[1][1]);
        }
        __syncthreads();   // compute done: As free for next tile, Cs free to write

#pragma unroll
        for (int i = 0; i < 2; i++)
#pragma unroll
            for (int j = 0; j < 2; j++)
                wmma::store_matrix_sync(&Cs[(wr * 32 + i * 16) * 132 + col0 + j * 16],
                                        acc[i][j], 132, wmma::mem_row_major);
        __syncthreads();

        const size_t outBase = (size_t)rowBase * D;
        for (int g = tid; g < 64 * 32; g += 256) {
            int r  = g >> 5;
            int c4 = (g & 31) * 4;
            union { __half2 h2[2]; uint2 u; } pk;
            pk.h2[0] = __floats2half2_rn(Cs[r * 132 + c4 + 0], Cs[r * 132 + c4 + 1]);
            pk.h2[1] = __floats2half2_rn(Cs[r * 132 + c4 + 2], Cs[r * 132 + c4 + 3]);
            *(uint2*)&out[outBase + (size_t)r * D + c4] = pk.u;
        }
    }
}

// ---------------------------------------------------------------------------
__device__ __forceinline__ float4 ld_row4(const __half* __restrict__ xs, int r, int c4) {
    uint2 u = __ldg((const uint2*)(xs + (size_t)r * D + c4));
    __half2 h0 = *(__half2*)&u.x;
    __half2 h1 = *(__half2*)&u.y;
    float2 a0 = __half22float2(h0);
    float2 a1 = __half22float2(h1);
    return make_float4(a0.x, a0.y, a1.x, a1.y);
}

// Gather: one warp per node, 32 lanes x 8 B, 4 edges in flight, fp32 accum.
// SRC_SCALE: multiply each message by dinv[src].
// OUT_HALF : write fp16(result * dinv[node]) as next layer's GEMM input.
template <bool SRC_SCALE, bool OUT_HALF>
__global__ void k_gather(const __half* __restrict__ xs, const float* __restrict__ b,
                         const float* __restrict__ a, float* __restrict__ outf,
                         __half* __restrict__ outh) {
    int node = (blockIdx.x * blockDim.x + threadIdx.x) >> 5;
    int lane = threadIdx.x & 31;
    if (node >= N_NODES) return;
    const int c4 = lane * 4;
    const float di = g_dinv[node];

    float4 self = ld_row4(xs, node, c4);   // self loop
    float sw = SRC_SCALE ? di : 1.0f;
    float4 acc = make_float4(self.x * sw, self.y * sw, self.z * sw, self.w * sw);

    const int s = node * CAP;
    const int e = s + g_cur[node];
    int i = s;
    for (; i + 4 <= e; i += 4) {
        int r0 = __ldg(&g_bkt[i]);
        int r1 = __ldg(&g_bkt[i + 1]);
        int r2 = __ldg(&g_bkt[i + 2]);
        int r3 = __ldg(&g_bkt[i + 3]);
        float4 v0 = ld_row4(xs, r0, c4);
        float4 v1 = ld_row4(xs, r1, c4);
        float4 v2 = ld_row4(xs, r2, c4);
        float4 v3 = ld_row4(xs, r3, c4);
        if (SRC_SCALE) {
            float w0 = __ldg(&g_dinv[r0]);
            float w1 = __ldg(&g_dinv[r1]);
            float w2 = __ldg(&g_dinv[r2]);
            float w3 = __ldg(&g_dinv[r3]);
            acc.x = fmaf(v0.x, w0, fmaf(v1.x, w1, fmaf(v2.x, w2, fmaf(v3.x, w3, acc.x))));
            acc.y = fmaf(v0.y, w0, fmaf(v1.y, w1, fmaf(v2.y, w2, fmaf(v3.y, w3, acc.y))));
            acc.z = fmaf(v0.z, w0, fmaf(v1.z, w1, fmaf(v2.z, w2, fmaf(v3.z, w3, acc.z))));
            acc.w = fmaf(v0.w, w0, fmaf(v1.w, w1, fmaf(v2.w, w2, fmaf(v3.w, w3, acc.w))));
        } else {
            acc.x += (v0.x + v1.x) + (v2.x + v3.x);
            acc.y += (v0.y + v1.y) + (v2.y + v3.y);
            acc.z += (v0.z + v1.z) + (v2.z + v3.z);
            acc.w += (v0.w + v1.w) + (v2.w + v3.w);
        }
    }
    for (; i < e; i++) {
        int r0 = __ldg(&g_bkt[i]);
        float4 v0 = ld_row4(xs, r0, c4);
        float w0 = SRC_SCALE ? __ldg(&g_dinv[r0]) : 1.0f;
        acc.x = fmaf(v0.x, w0, acc.x);
        acc.y = fmaf(v0.y, w0, acc.y);
        acc.z = fmaf(v0.z, w0, acc.z);
        acc.w = fmaf(v0.w, w0, acc.w);
    }

    float4 bb = *(const float4*)&b[c4];
    float4 aa = *(const float4*)&a[c4];
    float4 o;
    o.x = fmaf(di, acc.x, bb.x); o.x = (o.x >= 0.f) ? o.x : aa.x * o.x;
    o.y = fmaf(di, acc.y, bb.y); o.y = (o.y >= 0.f) ? o.y : aa.y * o.y;
    o.z = fmaf(di, acc.z, bb.z); o.z = (o.z >= 0.f) ? o.z : aa.z * o.z;
    o.w = fmaf(di, acc.w, bb.w); o.w = (o.w >= 0.f) ? o.w : aa.w * o.w;

    if (OUT_HALF) {
        union { __half2 h2[2]; uint2 u; } pk;
        pk.h2[0] = __floats2half2_rn(o.x * di, o.y * di);
        pk.h2[1] = __floats2half2_rn(o.z * di, o.w * di);
        *(uint2*)&outh[(size_t)node * D + c4] = pk.u;
    } else {
        *(float4*)&outf[(size_t)node * D + c4] = o;
    }
}

// ---------------------------------------------------------------------------
extern "C" void kernel_launch(void* const* d_in, const int* in_sizes, int n_in,
                              void* d_out, int out_size) {
    const float* x  = (const float*)d_in[0];
    const int*   ei = (const int*)  d_in[1];
    const float* W1 = (const float*)d_in[2];
    const float* b1 = (const float*)d_in[3];
    const float* a1 = (const float*)d_in[4];
    const float* W2 = (const float*)d_in[5];
    const float* b2 = (const float*)d_in[6];
    const float* a2 = (const float*)d_in[7];
    float* out = (float*)d_out;

    const int4* row4 = (const int4*)ei;               // edge_index[0] = sources
    const int4* col4 = (const int4*)(ei + N_EDGES);   // edge_index[1] = targets

    __half *a_ptr, *xs_ptr, *w2_ptr;  int *cur_ptr;
    cudaGetSymbolAddress((void**)&a_ptr,   g_a);
    cudaGetSymbolAddress((void**)&xs_ptr,  g_xsh);
    cudaGetSymbolAddress((void**)&w2_ptr,  g_w2);
    cudaGetSymbolAddress((void**)&cur_ptr, g_cur);

    // one-time setup (host resources + func attributes; first call is uncaptured)
    static cudaStream_t s_side = nullptr;
    static cudaEvent_t  ev_fork = nullptr, ev_join = nullptr;
    static bool attr_done = false;
    if (s_side == nullptr)  cudaStreamCreateWithFlags(&s_side, cudaStreamNonBlocking);
    if (ev_fork == nullptr) cudaEventCreateWithFlags(&ev_fork, cudaEventDisableTiming);
    if (ev_join == nullptr) cudaEventCreateWithFlags(&ev_join, cudaEventDisableTiming);
    if (!attr_done) {
        cudaFuncSetAttribute(k_gemm<true>,
                             cudaFuncAttributeMaxDynamicSharedMemorySize, GEMM_SMEM);
        cudaFuncSetAttribute(k_gemm<false>,
                             cudaFuncAttributeMaxDynamicSharedMemorySize, GEMM_SMEM);
        attr_done = true;
    }

    const int e4blocks      = (N_EDGES / 4 + 255) / 256;
    const int gather_blocks = (N_NODES * 32 + 255) / 256;

    // ---- fork: bucket build + W2 convert on side stream ----
    cudaEventRecord(ev_fork, 0);
    cudaStreamWaitEvent(s_side, ev_fork, 0);
    cudaMemsetAsync(cur_ptr, 0, N_NODES * sizeof(int), s_side);
    k_bucket <<<e4blocks, 256, 0, s_side>>>(row4, col4);
    k_dinv   <<<(N_NODES + 255) / 256, 256, 0, s_side>>>();
    k_conv_w2<<<(D * D + 255) / 256, 256, 0, s_side>>>(W2);
    cudaEventRecord(ev_join, s_side);

    // ---- main stream: layer-1 GEMM directly from fp32 x and W1 ----
    k_gemm<true> <<<GEMM_GRID, 256, GEMM_SMEM>>>(x, W1, xs_ptr);

    // ---- join: gather-1 needs buckets + dinv + messages ----
    cudaStreamWaitEvent(0, ev_join, 0);
    k_gather<true, true>  <<<gather_blocks, 256>>>(xs_ptr, b1, a1, nullptr, a_ptr);

    // ---- layer 2 (serial on main stream; xs reuse is safe) ----
    k_gemm<false><<<GEMM_GRID, 256, GEMM_SMEM>>>(a_ptr, w2_ptr, xs_ptr);
    k_gather<false, false><<<gather_blocks, 256>>>(xs_ptr, b2, a2, out, nullptr);
}